// round 1
// baseline (speedup 1.0000x reference)
#include <cuda_runtime.h>
#include <cuda_bf16.h>
#include <stdint.h>

// Triangle scatter + symmetrize:
//   out[b, i, j] = (i == j) ? 0 : in[b, tri(max(i,j), min(i,j))]
//   tri(r, c) = r*(r-1)/2 + c   (strict lower triangle, row-major)
//
// BATCH = 32768, N = 64, NC2 = 2016.
// One CTA per batch row. Input row staged in smem (8064 B), output row
// (16 KB) written fully coalesced as float4.

#define N_ATOMS 64
#define NC2     2016            // 64*63/2
#define OUT_ROW (N_ATOMS * N_ATOMS)  // 4096
#define THREADS 256

__global__ __launch_bounds__(THREADS)
void Triangle_39719857553609_kernel(const float* __restrict__ in,
                                    float* __restrict__ out) {
    __shared__ float s[NC2];

    const int b = blockIdx.x;
    const int tid = threadIdx.x;

    // ---- Stage input row into smem, vectorized (2016 floats = 504 float4) ----
    const float4* in_row = reinterpret_cast<const float4*>(in + (size_t)b * NC2);
    float4* s4 = reinterpret_cast<float4*>(s);
    #pragma unroll
    for (int t = tid; t < NC2 / 4; t += THREADS) {
        s4[t] = in_row[t];
    }
    __syncthreads();

    // ---- Emit 64x64 output tile: 1024 float4 per row, 4 per thread ----
    float4* out_row = reinterpret_cast<float4*>(out + (size_t)b * OUT_ROW);

    #pragma unroll
    for (int k = 0; k < 4; k++) {
        const int q  = tid + k * THREADS;   // float4 index in [0, 1024)
        const int i  = q >> 4;              // output row   (q*4 / 64)
        const int j0 = (q & 15) << 2;       // output col base

        float4 r;
        float* rp = reinterpret_cast<float*>(&r);
        #pragma unroll
        for (int e = 0; e < 4; e++) {
            const int j = j0 + e;
            float v = 0.0f;
            if (i != j) {
                const int hi = i > j ? i : j;
                const int lo = i > j ? j : i;
                v = s[(hi * (hi - 1)) / 2 + lo];
            }
            rp[e] = v;
        }
        out_row[q] = r;
    }
}

extern "C" void kernel_launch(void* const* d_in, const int* in_sizes, int n_in,
                              void* d_out, int out_size) {
    const float* in = (const float*)d_in[0];
    float* out = (float*)d_out;
    const int batch = in_sizes[0] / NC2;   // 32768
    Triangle_39719857553609_kernel<<<batch, THREADS>>>(in, out);
}